// round 16
// baseline (speedup 1.0000x reference)
#include <cuda_runtime.h>
#include <cuda_bf16.h>
#include <cstdint>

// ============================================================================
// Relative-position MHA (NO softmax) — algebraic restructure.
//   GEMMs: split-bf16 (3-term) mma.sync, single fp32 pass (hi+lo tiles)
//   mid_kernel: Q-proj GEMM + K^T V + W0 bf16 pre-conversion, one launch
//   stage3: band/bucket via mma.sync; in-block ktv reduce + offset scans;
//           shared in-place prefix scan for the tail
//   final: BM=64 BN=32, 512 blocks, 4/SM — latency-bound tail needs overlap
// ============================================================================

#define D_MODEL 256
#define HEADS   8
#define DH      32
#define SEQ     2048
#define BATCH   2
#define MAXREL  10
#define NT      21
#define BHN     (BATCH*HEADS)
#define MROWS   (BATCH*SEQ)
#define NC64    32
#define QT      64
#define INV_SCALE (1.0f/16.0f)
#define X2W 512                     // split layout: [hi(256) | lo(256)]

// -------------------- scratch (device globals; no allocs) -------------------
__device__ float g_Qp[MROWS*D_MODEL];
__device__ float g_Kp[MROWS*D_MODEL];
__device__ float g_Vp[MROWS*D_MODEL];
__device__ __align__(16) __nv_bfloat16 g_X2[MROWS*X2W];
__device__ __align__(16) __nv_bfloat16 g_W0b[D_MODEL*X2W];   // W0 split bf16
__device__ float g_csumK[BHN*NC64*DH];
__device__ float g_csumV[BHN*NC64*DH];
__device__ __align__(16) float g_ktvp[16*BHN*DH*DH];   // 1 slab per (chunk,bh)

// ============================================================================
// helpers
// ============================================================================
__device__ __forceinline__ uint2 cvt4(const float4 x, bool lo_part)
{
    union { __nv_bfloat16 h[4]; uint2 u; } r;
    float xs[4] = {x.x, x.y, x.z, x.w};
#pragma unroll
    for (int j = 0; j < 4; j++) {
        __nv_bfloat16 hi = __float2bfloat16(xs[j]);
        r.h[j] = lo_part ? __float2bfloat16(xs[j] - __bfloat162float(hi)) : hi;
    }
    return r.u;
}

__device__ __forceinline__ void hilo2(float a, float b, uint32_t& h, uint32_t& l)
{
    const __nv_bfloat16 ah = __float2bfloat16(a), bh_ = __float2bfloat16(b);
    const __nv_bfloat16 al = __float2bfloat16(a - __bfloat162float(ah));
    const __nv_bfloat16 bl = __float2bfloat16(b - __bfloat162float(bh_));
    union { __nv_bfloat162 v; uint32_t u; } H, L;
    H.v = __halves2bfloat162(ah, bh_);
    L.v = __halves2bfloat162(al, bl);
    h = H.u; l = L.u;
}

__device__ __forceinline__ uint32_t hi2(float a, float b)
{
    uint32_t u;
    asm("cvt.rn.bf16x2.f32 %0, %1, %2;" : "=r"(u) : "f"(b), "f"(a));
    return u;
}

#define MMA16816(C, A, B0, B1) \
    asm volatile("mma.sync.aligned.m16n8k16.row.col.f32.bf16.bf16.f32 " \
        "{%0,%1,%2,%3},{%4,%5,%6,%7},{%8,%9},{%0,%1,%2,%3};" \
        : "+f"((C)[0]), "+f"((C)[1]), "+f"((C)[2]), "+f"((C)[3]) \
        : "r"((A)[0]), "r"((A)[1]), "r"((A)[2]), "r"((A)[3]), "r"(B0), "r"(B1))

#define LDMX4(R, addr) \
    asm volatile("ldmatrix.sync.aligned.m8n8.x4.shared.b16 {%0,%1,%2,%3}, [%4];" \
        : "=r"((R)[0]), "=r"((R)[1]), "=r"((R)[2]), "=r"((R)[3]) : "r"(addr))

// ============================================================================
// GEMM body (BM=128): C[M,256] = split(A).split(W)^T + bias; single fp32 pass.
// ============================================================================
struct GemmSmem {
    __nv_bfloat16 As[2][128*72];
    __nv_bfloat16 Bs[2][64*72];
};

__device__ __forceinline__ void mma_gemm_body128(
    const float* __restrict__ A, const float* __restrict__ W,
    const float* __restrict__ bias, float* __restrict__ C,
    const int m0, const int n0)
{
    extern __shared__ __align__(16) char gsm_raw[];
    GemmSmem* gsm = reinterpret_cast<GemmSmem*>(gsm_raw);

    const int tid = threadIdx.x;
    const int w = tid >> 5, lane = tid & 31;
    const int wm = (w >> 1) * 32, wn = (w & 1) * 32;

    float acc[2][4][4];
#pragma unroll
    for (int a = 0; a < 2; a++)
#pragma unroll
        for (int j = 0; j < 4; j++)
#pragma unroll
            for (int e = 0; e < 4; e++) acc[a][j][e] = 0.f;

    const int a_row = (lane & 15), a_c8 = (lane >> 4) << 3;
    const int b_row = (lane & 7) + ((lane >> 4) << 3), b_c8 = ((lane >> 3) & 1) << 3;

    float4 aF[4]; float4 bF[2];

    auto LDG = [&](int kt) {
        const int sc = kt*32;
#pragma unroll
        for (int r = 0; r < 4; r++) {
            const int id = tid + r*256, row = id >> 3, c4 = (id & 7) << 2;
            aF[r] = *reinterpret_cast<const float4*>(&A[(size_t)(m0+row)*256 + sc + c4]);
        }
#pragma unroll
        for (int r = 0; r < 2; r++) {
            const int id = tid + r*256, row = id >> 3, c4 = (id & 7) << 2;
            bF[r] = *reinterpret_cast<const float4*>(&W[(size_t)(n0+row)*256 + sc + c4]);
        }
    };
    auto STS = [&](int buf) {
#pragma unroll
        for (int r = 0; r < 4; r++) {
            const int id = tid + r*256, row = id >> 3, c4 = (id & 7) << 2;
            *reinterpret_cast<uint2*>(&gsm->As[buf][row*72 + c4])      = cvt4(aF[r], false);
            *reinterpret_cast<uint2*>(&gsm->As[buf][row*72 + 32 + c4]) = cvt4(aF[r], true);
        }
#pragma unroll
        for (int r = 0; r < 2; r++) {
            const int id = tid + r*256, row = id >> 3, c4 = (id & 7) << 2;
            *reinterpret_cast<uint2*>(&gsm->Bs[buf][row*72 + c4])      = cvt4(bF[r], false);
            *reinterpret_cast<uint2*>(&gsm->Bs[buf][row*72 + 32 + c4]) = cvt4(bF[r], true);
        }
    };

    LDG(0); STS(0);
    __syncthreads();

    for (int i = 0; i < 8; i++) {
        if (i+1 < 8) LDG(i+1);
        const int buf = i & 1;
#pragma unroll
        for (int kk = 0; kk < 32; kk += 16) {
            uint32_t ah[2][4], al[2][4], bh[2][4], bl[2][4];
#pragma unroll
            for (int am = 0; am < 2; am++) {
                LDMX4(ah[am], (uint32_t)__cvta_generic_to_shared(
                    &gsm->As[buf][(wm + am*16 + a_row)*72 + kk + a_c8]));
                LDMX4(al[am], (uint32_t)__cvta_generic_to_shared(
                    &gsm->As[buf][(wm + am*16 + a_row)*72 + 32 + kk + a_c8]));
            }
#pragma unroll
            for (int bn = 0; bn < 2; bn++) {
                LDMX4(bh[bn], (uint32_t)__cvta_generic_to_shared(
                    &gsm->Bs[buf][(wn + bn*16 + b_row)*72 + kk + b_c8]));
                LDMX4(bl[bn], (uint32_t)__cvta_generic_to_shared(
                    &gsm->Bs[buf][(wn + bn*16 + b_row)*72 + 32 + kk + b_c8]));
            }
#pragma unroll
            for (int am = 0; am < 2; am++)
#pragma unroll
                for (int j = 0; j < 4; j++) {
                    const uint32_t B0h = bh[j>>1][(j&1)*2], B1h = bh[j>>1][(j&1)*2+1];
                    const uint32_t B0l = bl[j>>1][(j&1)*2], B1l = bl[j>>1][(j&1)*2+1];
                    MMA16816(acc[am][j], ah[am], B0h, B1h);
                    MMA16816(acc[am][j], al[am], B0h, B1h);
                    MMA16816(acc[am][j], ah[am], B0l, B1l);
                }
        }
        if (i+1 < 8) STS((i+1)&1);
        __syncthreads();
    }

    const int r = lane >> 2, cp = (lane & 3) * 2;
#pragma unroll
    for (int am = 0; am < 2; am++)
#pragma unroll
        for (int j = 0; j < 4; j++) {
            const int col = n0 + wn + j*8 + cp;
            const float bb0 = bias[col], bb1 = bias[col+1];
            const int row0 = m0 + wm + am*16 + r;
            *reinterpret_cast<float2*>(&C[(size_t)row0*256 + col]) =
                make_float2(acc[am][j][0] + bb0, acc[am][j][1] + bb1);
            *reinterpret_cast<float2*>(&C[(size_t)(row0+8)*256 + col]) =
                make_float2(acc[am][j][2] + bb0, acc[am][j][3] + bb1);
        }
}

__global__ __launch_bounds__(256, 2) void proj_kv_mma(
    const float* __restrict__ k,  const float* __restrict__ v,
    const float* __restrict__ Wk, const float* __restrict__ bk,
    const float* __restrict__ Wv, const float* __restrict__ bv)
{
    if (blockIdx.z == 0)
        mma_gemm_body128(k, Wk, bk, g_Kp, blockIdx.x*128, blockIdx.y*64);
    else
        mma_gemm_body128(v, Wv, bv, g_Vp, blockIdx.x*128, blockIdx.y*64);
}

// ============================================================================
// final GEMM: BM=64 BN=32, A/B prebuilt split-bf16, 512 blocks, 4/SM
// ============================================================================
struct Gemm64Smem {
    __nv_bfloat16 As[2][64*72];
    __nv_bfloat16 Bs[2][32*72];
};

__global__ __launch_bounds__(256, 4) void final_mma(
    const float* __restrict__ b0, float* __restrict__ out)
{
    extern __shared__ __align__(16) char gsm_raw[];
    Gemm64Smem* gsm = reinterpret_cast<Gemm64Smem*>(gsm_raw);
    const __nv_bfloat16* A = g_X2;
    const __nv_bfloat16* B = g_W0b;

    const int tid = threadIdx.x;
    const int m0 = blockIdx.x*64, n0 = blockIdx.y*32;
    const int w = tid >> 5, lane = tid & 31;
    const int wm = (w >> 1) * 16, wn = (w & 1) * 16;   // warp tile 16x16

    float acc[2][4];
#pragma unroll
    for (int j = 0; j < 2; j++)
#pragma unroll
        for (int e = 0; e < 4; e++) acc[j][e] = 0.f;

    const int a_row = (lane & 15), a_c8 = (lane >> 4) << 3;
    const int b_row = (lane & 7) + ((lane >> 4) << 3), b_c8 = ((lane >> 3) & 1) << 3;

    uint4 aH, aL, bH, bL;

    auto LDG = [&](int kt) {
        const int sc = kt*32;
        const int row = tid >> 2, c8 = (tid & 3) << 3;
        aH = *reinterpret_cast<const uint4*>(&A[(size_t)(m0+row)*X2W + sc + c8]);
        aL = *reinterpret_cast<const uint4*>(&A[(size_t)(m0+row)*X2W + 256 + sc + c8]);
        if (tid < 128) {
            bH = *reinterpret_cast<const uint4*>(&B[(size_t)(n0+row)*X2W + sc + c8]);
            bL = *reinterpret_cast<const uint4*>(&B[(size_t)(n0+row)*X2W + 256 + sc + c8]);
        }
    };
    auto STS = [&](int buf) {
        const int row = tid >> 2, c8 = (tid & 3) << 3;
        *reinterpret_cast<uint4*>(&gsm->As[buf][row*72 + c8])      = aH;
        *reinterpret_cast<uint4*>(&gsm->As[buf][row*72 + 32 + c8]) = aL;
        if (tid < 128) {
            *reinterpret_cast<uint4*>(&gsm->Bs[buf][row*72 + c8])      = bH;
            *reinterpret_cast<uint4*>(&gsm->Bs[buf][row*72 + 32 + c8]) = bL;
        }
    };

    LDG(0); STS(0);
    __syncthreads();

    for (int i = 0; i < 8; i++) {
        if (i+1 < 8) LDG(i+1);
        const int buf = i & 1;
#pragma unroll
        for (int kk = 0; kk < 32; kk += 16) {
            uint32_t ah[4], al[4], bh[4], bl[4];
            LDMX4(ah, (uint32_t)__cvta_generic_to_shared(
                &gsm->As[buf][(wm + a_row)*72 + kk + a_c8]));
            LDMX4(al, (uint32_t)__cvta_generic_to_shared(
                &gsm->As[buf][(wm + a_row)*72 + 32 + kk + a_c8]));
            LDMX4(bh, (uint32_t)__cvta_generic_to_shared(
                &gsm->Bs[buf][(wn + b_row)*72 + kk + b_c8]));
            LDMX4(bl, (uint32_t)__cvta_generic_to_shared(
                &gsm->Bs[buf][(wn + b_row)*72 + 32 + kk + b_c8]));
#pragma unroll
            for (int j = 0; j < 2; j++) {
                const uint32_t B0h = bh[j*2], B1h = bh[j*2+1];
                const uint32_t B0l = bl[j*2], B1l = bl[j*2+1];
                MMA16816(acc[j], ah, B0h, B1h);
                MMA16816(acc[j], al, B0h, B1h);
                MMA16816(acc[j], ah, B0l, B1l);
            }
        }
        if (i+1 < 8) STS((i+1)&1);
        __syncthreads();
    }

    const int r = lane >> 2, cp = (lane & 3) * 2;
#pragma unroll
    for (int j = 0; j < 2; j++) {
        const int col = n0 + wn + j*8 + cp;
        const float bb0 = b0[col], bb1 = b0[col+1];
        const int row0 = m0 + wm + r;
        *reinterpret_cast<float2*>(&out[(size_t)row0*256 + col]) =
            make_float2(acc[j][0] + bb0, acc[j][1] + bb1);
        *reinterpret_cast<float2*>(&out[(size_t)(row0+8)*256 + col]) =
            make_float2(acc[j][2] + bb0, acc[j][3] + bb1);
    }
}

// ============================================================================
// K^T V body: full in-block reduction to ONE slab per (chunk,bh)
// ============================================================================
struct KtvSmem {
    float Vsm[128*32];
    float red[4*1056];
    float redK[8*32], redV[8*32];
};

__device__ __forceinline__ void ktv_body(int idx, char* raw)
{
    KtvSmem* ks = reinterpret_cast<KtvSmem*>(raw);
    const int chunk = idx & 15, bh = idx >> 4;
    const int b = bh >> 3, h = bh & 7;
    const int tid = threadIdx.x, w = tid >> 5, lane = tid & 31;
    for (int i = tid; i < 128*32; i += 256) {
        const int row = i >> 5, d = i & 31;
        ks->Vsm[row*32 + d] = g_Vp[((size_t)(b*SEQ + chunk*128 + row))*D_MODEL + h*DH + d];
    }
    __syncthreads();
    float acc[32];
#pragma unroll
    for (int d = 0; d < 32; d++) acc[d] = 0.f;
    float ksum = 0.f, vsum = 0.f;
    const int r0 = w*16;
    for (int r = 0; r < 16; r++) {
        const float kreg = g_Kp[((size_t)(b*SEQ + chunk*128 + r0 + r))*D_MODEL + h*DH + lane];
        ksum += kreg;
        vsum += ks->Vsm[(r0 + r)*32 + lane];
#pragma unroll
        for (int d = 0; d < 32; d++) acc[d] += kreg * ks->Vsm[(r0 + r)*32 + d];
    }
    ks->redK[w*32 + lane] = ksum;
    ks->redV[w*32 + lane] = vsum;
    if (w >= 4) {
        float* p = &ks->red[(w-4)*1056 + lane*33];
#pragma unroll
        for (int d = 0; d < 32; d++) p[d] = acc[d];
    }
    __syncthreads();
    if (w < 4) {
        const float* p = &ks->red[w*1056 + lane*33];
#pragma unroll
        for (int d = 0; d < 32; d++) acc[d] += p[d];
    }
    if (w == 0) {
        float s = ks->redK[0*32+lane]+ks->redK[1*32+lane]+ks->redK[2*32+lane]+ks->redK[3*32+lane];
        g_csumK[(bh*NC64 + chunk*2)*DH + lane] = s;
    } else if (w == 1) {
        float s = ks->redK[4*32+lane]+ks->redK[5*32+lane]+ks->redK[6*32+lane]+ks->redK[7*32+lane];
        g_csumK[(bh*NC64 + chunk*2 + 1)*DH + lane] = s;
    } else if (w == 2) {
        float s = ks->redV[0*32+lane]+ks->redV[1*32+lane]+ks->redV[2*32+lane]+ks->redV[3*32+lane];
        g_csumV[(bh*NC64 + chunk*2)*DH + lane] = s;
    } else if (w == 3) {
        float s = ks->redV[4*32+lane]+ks->redV[5*32+lane]+ks->redV[6*32+lane]+ks->redV[7*32+lane];
        g_csumV[(bh*NC64 + chunk*2 + 1)*DH + lane] = s;
    }
    if (w == 2 || w == 3) {
        float* p = &ks->red[w*1056 + lane*33];
#pragma unroll
        for (int d = 0; d < 32; d++) p[d] = acc[d];
    }
    __syncthreads();
    if (w < 2) {
        const float* p = &ks->red[(w+2)*1056 + lane*33];
#pragma unroll
        for (int d = 0; d < 32; d++) acc[d] += p[d];
    }
    if (w == 1) {
        float* p = &ks->red[1*1056 + lane*33];
#pragma unroll
        for (int d = 0; d < 32; d++) p[d] = acc[d];
    }
    __syncthreads();
    if (w == 0) {
        const float* p = &ks->red[1*1056 + lane*33];
#pragma unroll
        for (int d = 0; d < 32; d++) acc[d] += p[d];
        float* o = &g_ktvp[((size_t)chunk*BHN + bh)*DH*DH + lane*DH];
#pragma unroll
        for (int d = 0; d < 32; d += 4)
            *reinterpret_cast<float4*>(&o[d]) =
                make_float4(acc[d], acc[d+1], acc[d+2], acc[d+3]);
    }
}

// mid_kernel: blocks 0..127 = Q proj GEMM, 128..383 = ktv, 384..385 = W0 cvt
__global__ __launch_bounds__(256, 2) void mid_kernel(
    const float* __restrict__ q, const float* __restrict__ Wq,
    const float* __restrict__ bq, const float* __restrict__ W0)
{
    extern __shared__ __align__(16) char dyn_raw[];
    if (blockIdx.x < 128) {
        mma_gemm_body128(q, Wq, bq, g_Qp,
                         (blockIdx.x & 31) * 128, (blockIdx.x >> 5) * 64);
    } else if (blockIdx.x < 384) {
        ktv_body(blockIdx.x - 128, dyn_raw);
    } else {
        // W0 -> split bf16 global ([hi|lo] per row)
        const int base = (blockIdx.x - 384) * 256 + threadIdx.x;   // 0..511
        for (int i4 = base; i4 < 16384; i4 += 512) {
            const float4 x = reinterpret_cast<const float4*>(W0)[i4];
            const int row = i4 >> 6, c4 = (i4 & 63) << 2;
            *reinterpret_cast<uint2*>(&g_W0b[(size_t)row*X2W + c4])       = cvt4(x, false);
            *reinterpret_cast<uint2*>(&g_W0b[(size_t)row*X2W + 256 + c4]) = cvt4(x, true);
        }
    }
}

// ============================================================================
// Stage 3 — self-contained: in-block ktv reduce + offset scans + MMA phases
// ============================================================================
struct S3Smem {
    float2 KVw[88*33];    // raw K/V, later in-place inclusive prefix (rows 0..83)
    float Tvs[21*33];
    float Srel[64*22];
    float Sval[64*22];
    float Osm [64*33];
    union __align__(16) {
        float Ktv[DH*DH];     // alive phase 0 -> phase 1  (float4 accessed)
        float Oband[64*33];   // alive phase 2a -> 2b
    } u;
    float2 scanTmp[8*32];
    float offK[32], offV[32], ktotS[32], vtotS[32];
};

__global__ __launch_bounds__(256, 4) void stage3(const float* __restrict__ tk,
                                                 const float* __restrict__ tv)
{
    extern __shared__ __align__(16) char s3_raw[];
    S3Smem* sm = reinterpret_cast<S3Smem*>(s3_raw);

    const int bh = blockIdx.y, b = bh >> 3, h = bh & 7;
    const int q0 = blockIdx.x * QT;
    const int tid = threadIdx.x, w = tid >> 5, lane = tid & 31;
    const int g = lane >> 2, tg = lane & 3;
    const int rm = (w & 3) * 16;

    // ---------------- phase 0: window loads + ktv reduce + offset scans ----
    for (int i = tid; i < 88*32; i += 256) {
        const int j = i >> 5, d = i & 31;
        const int kidx = q0 - MAXREL + j;
        float kv = 0.f, vv = 0.f;
        if (j < 84 && kidx >= 0 && kidx < SEQ) {
            const size_t gi = ((size_t)(b*SEQ + kidx))*D_MODEL + h*DH + d;
            kv = g_Kp[gi]; vv = g_Vp[gi];
        }
        sm->KVw[j*33 + d] = make_float2(kv, vv);
    }
    for (int i = tid; i < NT*32; i += 256)
        sm->Tvs[(i >> 5)*33 + (i & 31)] = tv[i];
    {   // ktv: sum 16 slabs, 4 consecutive floats per thread
        const int i4 = tid * 4;
        float4 s = make_float4(0.f, 0.f, 0.f, 0.f);
        for (int sl = 0; sl < 16; sl++) {
            const float4 p = *reinterpret_cast<const float4*>(
                &g_ktvp[((size_t)sl*BHN + bh)*DH*DH + i4]);
            s.x += p.x; s.y += p.y; s.z += p.z; s.w += p.w;
        }
        *reinterpret_cast<float4*>(&sm->u.Ktv[i4]) = s;
    }
    if (tid < 32) {
        const int d = tid, cq = q0 >> 6;
        float a = 0.f, cap = 0.f;
        for (int c = 0; c < NC64; c++) {
            if (c == cq) cap = a;
            a += g_csumK[(bh*NC64 + c)*DH + d];
        }
        sm->offK[d] = cap; sm->ktotS[d] = a;
    } else if (tid < 64) {
        const int d = tid - 32, cq = q0 >> 6;
        float a = 0.f, cap = 0.f;
        for (int c = 0; c < NC64; c++) {
            if (c == cq) cap = a;
            a += g_csumV[(bh*NC64 + c)*DH + d];
        }
        sm->offV[d] = cap; sm->vtotS[d] = a;
    }
    __syncthreads();

    // ---------------- phase 1 (balanced) ----------------
    uint32_t Ah[2][4], Al[2][4];
#pragma unroll
    for (int kc = 0; kc < 2; kc++) {
        const float* qb = &g_Qp[((size_t)(b*SEQ + q0 + rm + g))*D_MODEL + h*DH + kc*16 + tg*2];
        const float2 x0 = *reinterpret_cast<const float2*>(qb);
        const float2 x1 = *reinterpret_cast<const float2*>(qb + 8*D_MODEL);
        const float2 x2 = *reinterpret_cast<const float2*>(qb + 8);
        const float2 x3 = *reinterpret_cast<const float2*>(qb + 8*D_MODEL + 8);
        hilo2(x0.x, x0.y, Ah[kc][0], Al[kc][0]);
        hilo2(x1.x, x1.y, Ah[kc][1], Al[kc][1]);
        hilo2(x2.x, x2.y, Ah[kc][2], Al[kc][2]);
        hilo2(x3.x, x3.y, Ah[kc][3], Al[kc][3]);
    }

    if (w < 4) {
        // (a) raw band content scores -> Sval (2-term)
        float acc[5][4];
#pragma unroll
        for (int t = 0; t < 5; t++)
#pragma unroll
            for (int e = 0; e < 4; e++) acc[t][e] = 0.f;
#pragma unroll
        for (int tile = 0; tile < 5; tile++) {
            const int jw = rm + tile*8 + g;
#pragma unroll
            for (int kc = 0; kc < 2; kc++) {
                const int c0 = kc*16 + tg*2;
                const uint32_t B0h = hi2(sm->KVw[jw*33 + c0].x,     sm->KVw[jw*33 + c0 + 1].x);
                const uint32_t B1h = hi2(sm->KVw[jw*33 + c0 + 8].x, sm->KVw[jw*33 + c0 + 9].x);
                MMA16816(acc[tile], Ah[kc], B0h, B1h);
                MMA16816(acc[tile], Al[kc], B0h, B1h);
            }
        }
#pragma unroll
        for (int tile = 0; tile < 5; tile++)
#pragma unroll
            for (int e = 0; e < 4; e++) {
                const int r_loc = g + (e >> 1)*8;
                const int jl = tile*8 + tg*2 + (e & 1);
                const int t = jl - r_loc;
                if (t >= 1 && t <= 19)
                    sm->Sval[(rm + r_loc)*22 + t] = acc[tile][e];
            }
        // (b) Osm tiles 0..1 (cols 0..15), 3-term
        float accC[2][4];
#pragma unroll
        for (int t = 0; t < 2; t++)
#pragma unroll
            for (int e = 0; e < 4; e++) accC[t][e] = 0.f;
#pragma unroll
        for (int tile = 0; tile < 2; tile++) {
            const int n = tile*8 + g;
#pragma unroll
            for (int kc = 0; kc < 2; kc++) {
                const int e0 = kc*16 + tg*2;
                const float* cb = &sm->u.Ktv[e0*DH + n];
                uint32_t Bh[2], Bl[2];
                hilo2(cb[0],    cb[DH],   Bh[0], Bl[0]);
                hilo2(cb[8*DH], cb[9*DH], Bh[1], Bl[1]);
                MMA16816(accC[tile], Ah[kc], Bh[0], Bh[1]);
                MMA16816(accC[tile], Al[kc], Bh[0], Bh[1]);
                MMA16816(accC[tile], Ah[kc], Bl[0], Bl[1]);
            }
        }
#pragma unroll
        for (int tile = 0; tile < 2; tile++) {
            const int cc = tile*8 + tg*2;
            const int rr0 = rm + g, rr1 = rr0 + 8;
            sm->Osm[rr0*33 + cc]     = accC[tile][0];
            sm->Osm[rr0*33 + cc + 1] = accC[tile][1];
            sm->Osm[rr1*33 + cc]     = accC[tile][2];
            sm->Osm[rr1*33 + cc + 1] = accC[tile][3];
        }
    } else {
        // (a) Srel = Q.Tk^T (3-term)
        float accR[4][4];
#pragma unroll
        for (int t = 0; t < 4; t++)
#pragma unroll
            for (int e = 0; e < 4; e++) accR[t][e] = 0.f;
#pragma unroll
        for (int tile = 0; tile < 4; tile++) {
            const int n = tile*8 + g;
#pragma unroll
            for (int kc = 0; kc < 2; kc++) {
                const int e0 = kc*16 + tg*2;
                float r0 = 0.f, r1 = 0.f, r2 = 0.f, r3 = 0.f;
                if (n < NT) {
                    const float* tb = &tk[n*32 + e0];
                    r0 = tb[0]; r1 = tb[1]; r2 = tb[8]; r3 = tb[9];
                }
                uint32_t Bh[2], Bl[2];
                hilo2(r0, r1, Bh[0], Bl[0]);
                hilo2(r2, r3, Bh[1], Bl[1]);
                MMA16816(accR[tile], Ah[kc], Bh[0], Bh[1]);
                MMA16816(accR[tile], Al[kc], Bh[0], Bh[1]);
                MMA16816(accR[tile], Ah[kc], Bl[0], Bl[1]);
            }
        }
#pragma unroll
        for (int tile = 0; tile < 4; tile++) {
            const int cc = tile*8 + tg*2;
            const int rr0 = rm + g, rr1 = rr0 + 8;
            if (cc <= 20) {
                sm->Srel[rr0*22 + cc] = accR[tile][0];
                sm->Srel[rr1*22 + cc] = accR[tile][2];
            }
            if (cc + 1 <= 20) {
                sm->Srel[rr0*22 + cc + 1] = accR[tile][1];
                sm->Srel[rr1*22 + cc + 1] = accR[tile][3];
            }
        }
        // (b) Osm tiles 2..3 (cols 16..31), 3-term
        float accC[2][4];
#pragma unroll
        for (int t = 0; t < 2; t++)
#pragma unroll
            for (int e = 0; e < 4; e++) accC[t][e] = 0.f;
#pragma unroll
        for (int tile = 2; tile < 4; tile++) {
            const int n = tile*8 + g;
#pragma unroll
            for (int kc = 0; kc < 2; kc++) {
                const int e0 = kc*16 + tg*2;
                const float* cb = &sm->u.Ktv[e0*DH + n];
                uint32_t Bh[2], Bl[2];
                hilo2(cb[0],    cb[DH],   Bh[0], Bl[0]);
                hilo2(cb[8*DH], cb[9*DH], Bh[1], Bl[1]);
                MMA16816(accC[tile-2], Ah[kc], Bh[0], Bh[1]);
                MMA16816(accC[tile-2], Al[kc], Bh[0], Bh[1]);
                MMA16816(accC[tile-2], Ah[kc], Bl[0], Bl[1]);
            }
        }
#pragma unroll
        for (int tile = 2; tile < 4; tile++) {
            const int cc = tile*8 + tg*2;
            const int rr0 = rm + g, rr1 = rr0 + 8;
            sm->Osm[rr0*33 + cc]     = accC[tile-2][0];
            sm->Osm[rr0*33 + cc + 1] = accC[tile-2][1];
            sm->Osm[rr1*33 + cc]     = accC[tile-2][2];
            sm->Osm[rr1*33 + cc + 1] = accC[tile-2][3];
        }
    }
    __syncthreads();

    // ---------------- phase 2a: band + bucket MMAs -------------------------
    if (w < 4) {
        // Oband[r,d] = sum_t Srel[r,t] * V[r+t, d]   (2-term)
        float acc[4][4];
#pragma unroll
        for (int j = 0; j < 4; j++)
#pragma unroll
            for (int e = 0; e < 4; e++) acc[j][e] = 0.f;
#pragma unroll
        for (int k0 = 0; k0 < 48; k0 += 16) {
            uint32_t A_h[4], A_l[4];
            {
                auto aval = [&](int rl, int kk)->float {
                    const int t = kk - rl;
                    return (t >= 1 && t <= 19) ? sm->Srel[(rm+rl)*22 + t] : 0.f;
                };
                hilo2(aval(g,   k0+tg*2),   aval(g,   k0+tg*2+1), A_h[0], A_l[0]);
                hilo2(aval(g+8, k0+tg*2),   aval(g+8, k0+tg*2+1), A_h[1], A_l[1]);
                hilo2(aval(g,   k0+tg*2+8), aval(g,   k0+tg*2+9), A_h[2], A_l[2]);
                hilo2(aval(g+8, k0+tg*2+8), aval(g+8, k0+tg*2+9), A_h[3], A_l[3]);
            }
#pragma unroll
            for (int j = 0; j < 4; j++) {
                auto vval = [&](int kk)->float {
                    const int row = rm + kk;
                    return (row < 88) ? sm->KVw[row*33 + j*8 + g].y : 0.f;
                };
                const uint32_t B0h = hi2(vval(k0+tg*2),   vval(k0+tg*2+1));
                const uint32_t B1h = hi2(vval(k0+tg*2+8), vval(k0+tg*2+9));
                MMA16816(acc[j], A_h, B0h, B1h);
                MMA16816(acc[j], A_l, B0h, B1h);
            }
        }
#pragma unroll
        for (int j = 0; j < 4; j++) {
            const int cc = j*8 + tg*2;
            const int rr0 = rm + g, rr1 = rr0 + 8;
            sm->u.Oband[rr0*33 + cc]     = acc[j][0];
            sm->u.Oband[rr0*33 + cc + 1] = acc[j][1];
            sm->u.Oband[rr1*33 + cc]     = acc[j][2];
            sm->u.Oband[rr1*33 + cc + 1] = acc[j][3];
        }
    } else {
        // Osm[r,d] += sum_t (Sval+Srel masked)[r,t] * Tvs[t,d]   (1-term)
        float acc[4][4];
#pragma unroll
        for (int j = 0; j < 4; j++)
#pragma unroll
            for (int e = 0; e < 4; e++) acc[j][e] = 0.f;
#pragma unroll
        for (int k0 = 0; k0 < 32; k0 += 16) {
            uint32_t A_h[4];
            {
                auto aval = [&](int rl, int t)->float {
                    if (t < 1 || t > 19) return 0.f;
                    const int rr = rm + rl;
                    const int kidx = q0 + rr + t - MAXREL;
                    return (kidx >= 0 && kidx < SEQ)
                        ? (sm->Sval[rr*22 + t] + sm->Srel[rr*22 + t]) : 0.f;
                };
                A_h[0] = hi2(aval(g,   k0+tg*2),   aval(g,   k0+tg*2+1));
                A_h[1] = hi2(aval(g+8, k0+tg*2),   aval(g+8, k0+tg*2+1));
                A_h[2] = hi2(aval(g,   k0+tg*2+8), aval(g,   k0+tg*2+9));
                A_h[3] = hi2(aval(g+8, k0+tg*2+8), aval(g+8, k0+tg*2+9));
            }
#pragma unroll
            for (int j = 0; j < 4; j++) {
                auto tvv = [&](int t)->float {
                    return (t < NT) ? sm->Tvs[t*33 + j*8 + g] : 0.f;
                };
                const uint32_t B0h = hi2(tvv(k0+tg*2),   tvv(k0+tg*2+1));
                const uint32_t B1h = hi2(tvv(k0+tg*2+8), tvv(k0+tg*2+9));
                MMA16816(acc[j], A_h, B0h, B1h);
            }
        }
#pragma unroll
        for (int j = 0; j < 4; j++) {
            const int cc = j*8 + tg*2;
            const int rr0 = rm + g, rr1 = rr0 + 8;
            sm->Osm[rr0*33 + cc]     += acc[j][0];
            sm->Osm[rr0*33 + cc + 1] += acc[j][1];
            sm->Osm[rr1*33 + cc]     += acc[j][2];
            sm->Osm[rr1*33 + cc + 1] += acc[j][3];
        }
    }

    // ---------------- scan A: local 11-row sums (raw KVw reads) ------------
    {
        const int j0 = w * 11;
        const int jend = (j0 + 11 < 84) ? j0 + 11 : 84;
        float sk = 0.f, sv = 0.f;
        for (int j = j0; j < jend; j++) {
            const float2 p = sm->KVw[j*33 + lane];
            sk += p.x; sv += p.y;
        }
        sm->scanTmp[w*32 + lane] = make_float2(sk, sv);
    }
    __syncthreads();

    // ---------------- scan B: in-place inclusive prefix over rows 0..83 ----
    {
        float rk = 0.f, rv = 0.f;
        for (int w2 = 0; w2 < w; w2++) {
            const float2 p = sm->scanTmp[w2*32 + lane];
            rk += p.x; rv += p.y;
        }
        const int j0 = w * 11;
        const int jend = (j0 + 11 < 84) ? j0 + 11 : 84;
        for (int j = j0; j < jend; j++) {
            const float2 p = sm->KVw[j*33 + lane];
            rk += p.x; rv += p.y;
            sm->KVw[j*33 + lane] = make_float2(rk, rv);
        }
    }
    __syncthreads();

    // ---------------- phase 2b: thin scalar tail ---------------------------
    const float ktot = sm->ktotS[lane];
    const float vtot = sm->vtotS[lane];
    const float2 p9 = sm->KVw[9*33 + lane];
    const float baseK = sm->offK[lane] - p9.x, baseV = sm->offV[lane] - p9.y;

    for (int iq = 0; iq < 8; iq++) {
        const int r = iq*8 + w, q = q0 + r;
        const float2 Pr   = sm->KVw[r*33 + lane];
        const float2 Pr19 = sm->KVw[(r+19)*33 + lane];
        const float k1 = baseK + Pr.x,   v1 = baseV + Pr.y;
        const float k2 = baseK + Pr19.x, v2 = baseV + Pr19.y;

        const float qreg = g_Qp[((size_t)(b*SEQ + q))*D_MODEL + h*DH + lane];

        float pp = qreg * k1;
        float ss = qreg * (ktot - k2);
#pragma unroll
        for (int off = 16; off > 0; off >>= 1) {
            pp += __shfl_xor_sync(0xffffffffu, pp, off);
            ss += __shfl_xor_sync(0xffffffffu, ss, off);
        }

        const float s0  = sm->Srel[r*22 + 0];
        const float s20 = sm->Srel[r*22 + 20];
        float wv = sm->Osm[r*33 + lane] + sm->u.Oband[r*33 + lane]
                 + s0*v1 + s20*(vtot - v2);
        const float Sv0  = (q - MAXREL >= 0) ? (pp + (float)(q - MAXREL + 1)*s0) : 0.f;
        const float Sv20 = (q + MAXREL <= SEQ-1) ? (ss + (float)(SEQ - q - MAXREL)*s20) : 0.f;
        wv += Sv0 * sm->Tvs[lane] + Sv20 * sm->Tvs[20*33 + lane];

        const float o = wv * INV_SCALE;
        const __nv_bfloat16 hi = __float2bfloat16(o);
        const __nv_bfloat16 lo = __float2bfloat16(o - __bfloat162float(hi));
        const size_t rb = ((size_t)(b*SEQ + q))*X2W + h*DH + lane;
        g_X2[rb]       = hi;
        g_X2[rb + 256] = lo;
    }
}

// ============================================================================
// launch
// ============================================================================
extern "C" void kernel_launch(void* const* d_in, const int* in_sizes, int n_in,
                              void* d_out, int out_size)
{
    const float* q   = (const float*)d_in[0];
    const float* k   = (const float*)d_in[1];
    const float* v   = (const float*)d_in[2];
    const float* Wq  = (const float*)d_in[4];
    const float* bq  = (const float*)d_in[5];
    const float* Wk  = (const float*)d_in[6];
    const float* bk  = (const float*)d_in[7];
    const float* Wv  = (const float*)d_in[8];
    const float* bv  = (const float*)d_in[9];
    const float* W0  = (const float*)d_in[10];
    const float* b0  = (const float*)d_in[11];
    const float* tk  = (const float*)d_in[12];
    const float* tv  = (const float*)d_in[13];
    float* out = (float*)d_out;

    static int attr_done = 0;
    if (!attr_done) {
        cudaFuncSetAttribute(proj_kv_mma, cudaFuncAttributeMaxDynamicSharedMemorySize,
                             (int)sizeof(GemmSmem));
        cudaFuncSetAttribute(mid_kernel, cudaFuncAttributeMaxDynamicSharedMemorySize,
                             (int)sizeof(GemmSmem));
        cudaFuncSetAttribute(final_mma, cudaFuncAttributeMaxDynamicSharedMemorySize,
                             (int)sizeof(Gemm64Smem));
        cudaFuncSetAttribute(stage3, cudaFuncAttributeMaxDynamicSharedMemorySize,
                             (int)sizeof(S3Smem));
        attr_done = 1;
    }

    proj_kv_mma<<<dim3(MROWS/128, D_MODEL/64, 2), 256, sizeof(GemmSmem)>>>(
                   k, v, Wk, bk, Wv, bv);
    mid_kernel <<<386, 256, sizeof(GemmSmem)>>>(q, Wq, bq, W0);
    stage3     <<<dim3(SEQ/QT, BHN), 256, sizeof(S3Smem)>>>(tk, tv);
    final_mma  <<<dim3(MROWS/64, D_MODEL/32), 256, sizeof(Gemm64Smem)>>>(b0, out);
}

// round 17
// speedup vs baseline: 1.0713x; 1.0713x over previous
#include <cuda_runtime.h>
#include <cuda_bf16.h>
#include <cstdint>

// ============================================================================
// Relative-position MHA (NO softmax) — algebraic restructure.
//   GEMMs: split-bf16 (3-term) mma.sync, single fp32 pass (hi+lo tiles)
//   mid_kernel: Q-proj GEMM + K^T V + W0 bf16 pre-conversion, one launch
//   stage3: band/bucket via mma.sync; in-block ktv reduce + offset scans;
//           shared in-place prefix scan for the tail
//   final: BM=64 BN=64, prebuilt bf16 A/B, cp.async double-buffered pipeline
// ============================================================================

#define D_MODEL 256
#define HEADS   8
#define DH      32
#define SEQ     2048
#define BATCH   2
#define MAXREL  10
#define NT      21
#define BHN     (BATCH*HEADS)
#define MROWS   (BATCH*SEQ)
#define NC64    32
#define QT      64
#define INV_SCALE (1.0f/16.0f)
#define X2W 512                     // split layout: [hi(256) | lo(256)]

// -------------------- scratch (device globals; no allocs) -------------------
__device__ float g_Qp[MROWS*D_MODEL];
__device__ float g_Kp[MROWS*D_MODEL];
__device__ float g_Vp[MROWS*D_MODEL];
__device__ __align__(16) __nv_bfloat16 g_X2[MROWS*X2W];
__device__ __align__(16) __nv_bfloat16 g_W0b[D_MODEL*X2W];   // W0 split bf16
__device__ float g_csumK[BHN*NC64*DH];
__device__ float g_csumV[BHN*NC64*DH];
__device__ __align__(16) float g_ktvp[16*BHN*DH*DH];   // 1 slab per (chunk,bh)

// ============================================================================
// helpers
// ============================================================================
__device__ __forceinline__ uint2 cvt4(const float4 x, bool lo_part)
{
    union { __nv_bfloat16 h[4]; uint2 u; } r;
    float xs[4] = {x.x, x.y, x.z, x.w};
#pragma unroll
    for (int j = 0; j < 4; j++) {
        __nv_bfloat16 hi = __float2bfloat16(xs[j]);
        r.h[j] = lo_part ? __float2bfloat16(xs[j] - __bfloat162float(hi)) : hi;
    }
    return r.u;
}

__device__ __forceinline__ void hilo2(float a, float b, uint32_t& h, uint32_t& l)
{
    const __nv_bfloat16 ah = __float2bfloat16(a), bh_ = __float2bfloat16(b);
    const __nv_bfloat16 al = __float2bfloat16(a - __bfloat162float(ah));
    const __nv_bfloat16 bl = __float2bfloat16(b - __bfloat162float(bh_));
    union { __nv_bfloat162 v; uint32_t u; } H, L;
    H.v = __halves2bfloat162(ah, bh_);
    L.v = __halves2bfloat162(al, bl);
    h = H.u; l = L.u;
}

__device__ __forceinline__ uint32_t hi2(float a, float b)
{
    uint32_t u;
    asm("cvt.rn.bf16x2.f32 %0, %1, %2;" : "=r"(u) : "f"(b), "f"(a));
    return u;
}

__device__ __forceinline__ void cpasync16(uint32_t dst, const void* src)
{
    asm volatile("cp.async.cg.shared.global [%0], [%1], 16;"
                 :: "r"(dst), "l"(src));
}

#define MMA16816(C, A, B0, B1) \
    asm volatile("mma.sync.aligned.m16n8k16.row.col.f32.bf16.bf16.f32 " \
        "{%0,%1,%2,%3},{%4,%5,%6,%7},{%8,%9},{%0,%1,%2,%3};" \
        : "+f"((C)[0]), "+f"((C)[1]), "+f"((C)[2]), "+f"((C)[3]) \
        : "r"((A)[0]), "r"((A)[1]), "r"((A)[2]), "r"((A)[3]), "r"(B0), "r"(B1))

#define LDMX4(R, addr) \
    asm volatile("ldmatrix.sync.aligned.m8n8.x4.shared.b16 {%0,%1,%2,%3}, [%4];" \
        : "=r"((R)[0]), "=r"((R)[1]), "=r"((R)[2]), "=r"((R)[3]) : "r"(addr))

// ============================================================================
// GEMM body (BM=128): C[M,256] = split(A).split(W)^T + bias; single fp32 pass.
// ============================================================================
struct GemmSmem {
    __nv_bfloat16 As[2][128*72];
    __nv_bfloat16 Bs[2][64*72];
};

__device__ __forceinline__ void mma_gemm_body128(
    const float* __restrict__ A, const float* __restrict__ W,
    const float* __restrict__ bias, float* __restrict__ C,
    const int m0, const int n0)
{
    extern __shared__ __align__(16) char gsm_raw[];
    GemmSmem* gsm = reinterpret_cast<GemmSmem*>(gsm_raw);

    const int tid = threadIdx.x;
    const int w = tid >> 5, lane = tid & 31;
    const int wm = (w >> 1) * 32, wn = (w & 1) * 32;

    float acc[2][4][4];
#pragma unroll
    for (int a = 0; a < 2; a++)
#pragma unroll
        for (int j = 0; j < 4; j++)
#pragma unroll
            for (int e = 0; e < 4; e++) acc[a][j][e] = 0.f;

    const int a_row = (lane & 15), a_c8 = (lane >> 4) << 3;
    const int b_row = (lane & 7) + ((lane >> 4) << 3), b_c8 = ((lane >> 3) & 1) << 3;

    float4 aF[4]; float4 bF[2];

    auto LDG = [&](int kt) {
        const int sc = kt*32;
#pragma unroll
        for (int r = 0; r < 4; r++) {
            const int id = tid + r*256, row = id >> 3, c4 = (id & 7) << 2;
            aF[r] = *reinterpret_cast<const float4*>(&A[(size_t)(m0+row)*256 + sc + c4]);
        }
#pragma unroll
        for (int r = 0; r < 2; r++) {
            const int id = tid + r*256, row = id >> 3, c4 = (id & 7) << 2;
            bF[r] = *reinterpret_cast<const float4*>(&W[(size_t)(n0+row)*256 + sc + c4]);
        }
    };
    auto STS = [&](int buf) {
#pragma unroll
        for (int r = 0; r < 4; r++) {
            const int id = tid + r*256, row = id >> 3, c4 = (id & 7) << 2;
            *reinterpret_cast<uint2*>(&gsm->As[buf][row*72 + c4])      = cvt4(aF[r], false);
            *reinterpret_cast<uint2*>(&gsm->As[buf][row*72 + 32 + c4]) = cvt4(aF[r], true);
        }
#pragma unroll
        for (int r = 0; r < 2; r++) {
            const int id = tid + r*256, row = id >> 3, c4 = (id & 7) << 2;
            *reinterpret_cast<uint2*>(&gsm->Bs[buf][row*72 + c4])      = cvt4(bF[r], false);
            *reinterpret_cast<uint2*>(&gsm->Bs[buf][row*72 + 32 + c4]) = cvt4(bF[r], true);
        }
    };

    LDG(0); STS(0);
    __syncthreads();

    for (int i = 0; i < 8; i++) {
        if (i+1 < 8) LDG(i+1);
        const int buf = i & 1;
#pragma unroll
        for (int kk = 0; kk < 32; kk += 16) {
            uint32_t ah[2][4], al[2][4], bh[2][4], bl[2][4];
#pragma unroll
            for (int am = 0; am < 2; am++) {
                LDMX4(ah[am], (uint32_t)__cvta_generic_to_shared(
                    &gsm->As[buf][(wm + am*16 + a_row)*72 + kk + a_c8]));
                LDMX4(al[am], (uint32_t)__cvta_generic_to_shared(
                    &gsm->As[buf][(wm + am*16 + a_row)*72 + 32 + kk + a_c8]));
            }
#pragma unroll
            for (int bn = 0; bn < 2; bn++) {
                LDMX4(bh[bn], (uint32_t)__cvta_generic_to_shared(
                    &gsm->Bs[buf][(wn + bn*16 + b_row)*72 + kk + b_c8]));
                LDMX4(bl[bn], (uint32_t)__cvta_generic_to_shared(
                    &gsm->Bs[buf][(wn + bn*16 + b_row)*72 + 32 + kk + b_c8]));
            }
#pragma unroll
            for (int am = 0; am < 2; am++)
#pragma unroll
                for (int j = 0; j < 4; j++) {
                    const uint32_t B0h = bh[j>>1][(j&1)*2], B1h = bh[j>>1][(j&1)*2+1];
                    const uint32_t B0l = bl[j>>1][(j&1)*2], B1l = bl[j>>1][(j&1)*2+1];
                    MMA16816(acc[am][j], ah[am], B0h, B1h);
                    MMA16816(acc[am][j], al[am], B0h, B1h);
                    MMA16816(acc[am][j], ah[am], B0l, B1l);
                }
        }
        if (i+1 < 8) STS((i+1)&1);
        __syncthreads();
    }

    const int r = lane >> 2, cp = (lane & 3) * 2;
#pragma unroll
    for (int am = 0; am < 2; am++)
#pragma unroll
        for (int j = 0; j < 4; j++) {
            const int col = n0 + wn + j*8 + cp;
            const float bb0 = bias[col], bb1 = bias[col+1];
            const int row0 = m0 + wm + am*16 + r;
            *reinterpret_cast<float2*>(&C[(size_t)row0*256 + col]) =
                make_float2(acc[am][j][0] + bb0, acc[am][j][1] + bb1);
            *reinterpret_cast<float2*>(&C[(size_t)(row0+8)*256 + col]) =
                make_float2(acc[am][j][2] + bb0, acc[am][j][3] + bb1);
        }
}

__global__ __launch_bounds__(256, 2) void proj_kv_mma(
    const float* __restrict__ k,  const float* __restrict__ v,
    const float* __restrict__ Wk, const float* __restrict__ bk,
    const float* __restrict__ Wv, const float* __restrict__ bv)
{
    if (blockIdx.z == 0)
        mma_gemm_body128(k, Wk, bk, g_Kp, blockIdx.x*128, blockIdx.y*64);
    else
        mma_gemm_body128(v, Wv, bv, g_Vp, blockIdx.x*128, blockIdx.y*64);
}

// ============================================================================
// final GEMM (BM=64 BN=64): A/B prebuilt split-bf16, cp.async pipeline
// ============================================================================
struct Gemm64Smem {
    __nv_bfloat16 As[2][64*72];
    __nv_bfloat16 Bs[2][64*72];
};

__global__ __launch_bounds__(256, 3) void final_mma(
    const float* __restrict__ b0, float* __restrict__ out)
{
    extern __shared__ __align__(16) char gsm_raw[];
    Gemm64Smem* gsm = reinterpret_cast<Gemm64Smem*>(gsm_raw);
    const __nv_bfloat16* A = g_X2;
    const __nv_bfloat16* B = g_W0b;

    const int tid = threadIdx.x;
    const int m0 = blockIdx.x*64, n0 = blockIdx.y*64;
    const int w = tid >> 5, lane = tid & 31;
    const int wm = (w >> 1) * 16, wn = (w & 1) * 32;

    float acc[4][4];
#pragma unroll
    for (int j = 0; j < 4; j++)
#pragma unroll
        for (int e = 0; e < 4; e++) acc[j][e] = 0.f;

    const int a_row = (lane & 15), a_c8 = (lane >> 4) << 3;
    const int b_row = (lane & 7) + ((lane >> 4) << 3), b_c8 = ((lane >> 3) & 1) << 3;

    const int row = tid >> 2, c8 = (tid & 3) << 3;
    auto ISSUE = [&](int kt, int buf) {
        const int sc = kt*32;
        cpasync16((uint32_t)__cvta_generic_to_shared(&gsm->As[buf][row*72 + c8]),
                  &A[(size_t)(m0+row)*X2W + sc + c8]);
        cpasync16((uint32_t)__cvta_generic_to_shared(&gsm->As[buf][row*72 + 32 + c8]),
                  &A[(size_t)(m0+row)*X2W + 256 + sc + c8]);
        cpasync16((uint32_t)__cvta_generic_to_shared(&gsm->Bs[buf][row*72 + c8]),
                  &B[(size_t)(n0+row)*X2W + sc + c8]);
        cpasync16((uint32_t)__cvta_generic_to_shared(&gsm->Bs[buf][row*72 + 32 + c8]),
                  &B[(size_t)(n0+row)*X2W + 256 + sc + c8]);
        asm volatile("cp.async.commit_group;");
    };

    ISSUE(0, 0);

    for (int i = 0; i < 8; i++) {
        if (i+1 < 8) {
            ISSUE(i+1, (i+1)&1);   // buf (i+1)&1 freed by trailing barrier of iter i-1
            asm volatile("cp.async.wait_group 1;");
        } else {
            asm volatile("cp.async.wait_group 0;");
        }
        __syncthreads();           // group-i data visible to all threads
        const int buf = i & 1;
#pragma unroll
        for (int kk = 0; kk < 32; kk += 16) {
            uint32_t ah[4], al[4], bh[2][4], bl[2][4];
            LDMX4(ah, (uint32_t)__cvta_generic_to_shared(
                &gsm->As[buf][(wm + a_row)*72 + kk + a_c8]));
            LDMX4(al, (uint32_t)__cvta_generic_to_shared(
                &gsm->As[buf][(wm + a_row)*72 + 32 + kk + a_c8]));
#pragma unroll
            for (int bn = 0; bn < 2; bn++) {
                LDMX4(bh[bn], (uint32_t)__cvta_generic_to_shared(
                    &gsm->Bs[buf][(wn + bn*16 + b_row)*72 + kk + b_c8]));
                LDMX4(bl[bn], (uint32_t)__cvta_generic_to_shared(
                    &gsm->Bs[buf][(wn + bn*16 + b_row)*72 + 32 + kk + b_c8]));
            }
#pragma unroll
            for (int j = 0; j < 4; j++) {
                const uint32_t B0h = bh[j>>1][(j&1)*2], B1h = bh[j>>1][(j&1)*2+1];
                const uint32_t B0l = bl[j>>1][(j&1)*2], B1l = bl[j>>1][(j&1)*2+1];
                MMA16816(acc[j], ah, B0h, B1h);
                MMA16816(acc[j], al, B0h, B1h);
                MMA16816(acc[j], ah, B0l, B1l);
            }
        }
        __syncthreads();           // protect buf i before iter i+1 overwrites it
    }

    const int r = lane >> 2, cp = (lane & 3) * 2;
#pragma unroll
    for (int j = 0; j < 4; j++) {
        const int col = n0 + wn + j*8 + cp;
        const float bb0 = b0[col], bb1 = b0[col+1];
        const int row0 = m0 + wm + r;
        *reinterpret_cast<float2*>(&out[(size_t)row0*256 + col]) =
            make_float2(acc[j][0] + bb0, acc[j][1] + bb1);
        *reinterpret_cast<float2*>(&out[(size_t)(row0+8)*256 + col]) =
            make_float2(acc[j][2] + bb0, acc[j][3] + bb1);
    }
}

// ============================================================================
// K^T V body: full in-block reduction to ONE slab per (chunk,bh)
// ============================================================================
struct KtvSmem {
    float Vsm[128*32];
    float red[4*1056];
    float redK[8*32], redV[8*32];
};

__device__ __forceinline__ void ktv_body(int idx, char* raw)
{
    KtvSmem* ks = reinterpret_cast<KtvSmem*>(raw);
    const int chunk = idx & 15, bh = idx >> 4;
    const int b = bh >> 3, h = bh & 7;
    const int tid = threadIdx.x, w = tid >> 5, lane = tid & 31;
    for (int i = tid; i < 128*32; i += 256) {
        const int row = i >> 5, d = i & 31;
        ks->Vsm[row*32 + d] = g_Vp[((size_t)(b*SEQ + chunk*128 + row))*D_MODEL + h*DH + d];
    }
    __syncthreads();
    float acc[32];
#pragma unroll
    for (int d = 0; d < 32; d++) acc[d] = 0.f;
    float ksum = 0.f, vsum = 0.f;
    const int r0 = w*16;
    for (int r = 0; r < 16; r++) {
        const float kreg = g_Kp[((size_t)(b*SEQ + chunk*128 + r0 + r))*D_MODEL + h*DH + lane];
        ksum += kreg;
        vsum += ks->Vsm[(r0 + r)*32 + lane];
#pragma unroll
        for (int d = 0; d < 32; d++) acc[d] += kreg * ks->Vsm[(r0 + r)*32 + d];
    }
    ks->redK[w*32 + lane] = ksum;
    ks->redV[w*32 + lane] = vsum;
    if (w >= 4) {
        float* p = &ks->red[(w-4)*1056 + lane*33];
#pragma unroll
        for (int d = 0; d < 32; d++) p[d] = acc[d];
    }
    __syncthreads();
    if (w < 4) {
        const float* p = &ks->red[w*1056 + lane*33];
#pragma unroll
        for (int d = 0; d < 32; d++) acc[d] += p[d];
    }
    if (w == 0) {
        float s = ks->redK[0*32+lane]+ks->redK[1*32+lane]+ks->redK[2*32+lane]+ks->redK[3*32+lane];
        g_csumK[(bh*NC64 + chunk*2)*DH + lane] = s;
    } else if (w == 1) {
        float s = ks->redK[4*32+lane]+ks->redK[5*32+lane]+ks->redK[6*32+lane]+ks->redK[7*32+lane];
        g_csumK[(bh*NC64 + chunk*2 + 1)*DH + lane] = s;
    } else if (w == 2) {
        float s = ks->redV[0*32+lane]+ks->redV[1*32+lane]+ks->redV[2*32+lane]+ks->redV[3*32+lane];
        g_csumV[(bh*NC64 + chunk*2)*DH + lane] = s;
    } else if (w == 3) {
        float s = ks->redV[4*32+lane]+ks->redV[5*32+lane]+ks->redV[6*32+lane]+ks->redV[7*32+lane];
        g_csumV[(bh*NC64 + chunk*2 + 1)*DH + lane] = s;
    }
    if (w == 2 || w == 3) {
        float* p = &ks->red[w*1056 + lane*33];
#pragma unroll
        for (int d = 0; d < 32; d++) p[d] = acc[d];
    }
    __syncthreads();
    if (w < 2) {
        const float* p = &ks->red[(w+2)*1056 + lane*33];
#pragma unroll
        for (int d = 0; d < 32; d++) acc[d] += p[d];
    }
    if (w == 1) {
        float* p = &ks->red[1*1056 + lane*33];
#pragma unroll
        for (int d = 0; d < 32; d++) p[d] = acc[d];
    }
    __syncthreads();
    if (w == 0) {
        const float* p = &ks->red[1*1056 + lane*33];
#pragma unroll
        for (int d = 0; d < 32; d++) acc[d] += p[d];
        float* o = &g_ktvp[((size_t)chunk*BHN + bh)*DH*DH + lane*DH];
#pragma unroll
        for (int d = 0; d < 32; d += 4)
            *reinterpret_cast<float4*>(&o[d]) =
                make_float4(acc[d], acc[d+1], acc[d+2], acc[d+3]);
    }
}

// mid_kernel: blocks 0..127 = Q proj GEMM, 128..383 = ktv, 384..385 = W0 cvt
__global__ __launch_bounds__(256, 2) void mid_kernel(
    const float* __restrict__ q, const float* __restrict__ Wq,
    const float* __restrict__ bq, const float* __restrict__ W0)
{
    extern __shared__ __align__(16) char dyn_raw[];
    if (blockIdx.x < 128) {
        mma_gemm_body128(q, Wq, bq, g_Qp,
                         (blockIdx.x & 31) * 128, (blockIdx.x >> 5) * 64);
    } else if (blockIdx.x < 384) {
        ktv_body(blockIdx.x - 128, dyn_raw);
    } else {
        // W0 -> split bf16 global ([hi|lo] per row)
        const int base = (blockIdx.x - 384) * 256 + threadIdx.x;   // 0..511
        for (int i4 = base; i4 < 16384; i4 += 512) {
            const float4 x = reinterpret_cast<const float4*>(W0)[i4];
            const int row = i4 >> 6, c4 = (i4 & 63) << 2;
            *reinterpret_cast<uint2*>(&g_W0b[(size_t)row*X2W + c4])       = cvt4(x, false);
            *reinterpret_cast<uint2*>(&g_W0b[(size_t)row*X2W + 256 + c4]) = cvt4(x, true);
        }
    }
}

// ============================================================================
// Stage 3 — self-contained: in-block ktv reduce + offset scans + MMA phases
// ============================================================================
struct S3Smem {
    float2 KVw[88*33];    // raw K/V, later in-place inclusive prefix (rows 0..83)
    float Tvs[21*33];
    float Srel[64*22];
    float Sval[64*22];
    float Osm [64*33];
    union __align__(16) {
        float Ktv[DH*DH];     // alive phase 0 -> phase 1  (float4 accessed)
        float Oband[64*33];   // alive phase 2a -> 2b
    } u;
    float2 scanTmp[8*32];
    float offK[32], offV[32], ktotS[32], vtotS[32];
};

__global__ __launch_bounds__(256, 4) void stage3(const float* __restrict__ tk,
                                                 const float* __restrict__ tv)
{
    extern __shared__ __align__(16) char s3_raw[];
    S3Smem* sm = reinterpret_cast<S3Smem*>(s3_raw);

    const int bh = blockIdx.y, b = bh >> 3, h = bh & 7;
    const int q0 = blockIdx.x * QT;
    const int tid = threadIdx.x, w = tid >> 5, lane = tid & 31;
    const int g = lane >> 2, tg = lane & 3;
    const int rm = (w & 3) * 16;

    // ---------------- phase 0: window loads + ktv reduce + offset scans ----
    for (int i = tid; i < 88*32; i += 256) {
        const int j = i >> 5, d = i & 31;
        const int kidx = q0 - MAXREL + j;
        float kv = 0.f, vv = 0.f;
        if (j < 84 && kidx >= 0 && kidx < SEQ) {
            const size_t gi = ((size_t)(b*SEQ + kidx))*D_MODEL + h*DH + d;
            kv = g_Kp[gi]; vv = g_Vp[gi];
        }
        sm->KVw[j*33 + d] = make_float2(kv, vv);
    }
    for (int i = tid; i < NT*32; i += 256)
        sm->Tvs[(i >> 5)*33 + (i & 31)] = tv[i];
    {   // ktv: sum 16 slabs, 4 consecutive floats per thread
        const int i4 = tid * 4;
        float4 s = make_float4(0.f, 0.f, 0.f, 0.f);
        for (int sl = 0; sl < 16; sl++) {
            const float4 p = *reinterpret_cast<const float4*>(
                &g_ktvp[((size_t)sl*BHN + bh)*DH*DH + i4]);
            s.x += p.x; s.y += p.y; s.z += p.z; s.w += p.w;
        }
        *reinterpret_cast<float4*>(&sm->u.Ktv[i4]) = s;
    }
    if (tid < 32) {
        const int d = tid, cq = q0 >> 6;
        float a = 0.f, cap = 0.f;
        for (int c = 0; c < NC64; c++) {
            if (c == cq) cap = a;
            a += g_csumK[(bh*NC64 + c)*DH + d];
        }
        sm->offK[d] = cap; sm->ktotS[d] = a;
    } else if (tid < 64) {
        const int d = tid - 32, cq = q0 >> 6;
        float a = 0.f, cap = 0.f;
        for (int c = 0; c < NC64; c++) {
            if (c == cq) cap = a;
            a += g_csumV[(bh*NC64 + c)*DH + d];
        }
        sm->offV[d] = cap; sm->vtotS[d] = a;
    }
    __syncthreads();

    // ---------------- phase 1 (balanced) ----------------
    uint32_t Ah[2][4], Al[2][4];
#pragma unroll
    for (int kc = 0; kc < 2; kc++) {
        const float* qb = &g_Qp[((size_t)(b*SEQ + q0 + rm + g))*D_MODEL + h*DH + kc*16 + tg*2];
        const float2 x0 = *reinterpret_cast<const float2*>(qb);
        const float2 x1 = *reinterpret_cast<const float2*>(qb + 8*D_MODEL);
        const float2 x2 = *reinterpret_cast<const float2*>(qb + 8);
        const float2 x3 = *reinterpret_cast<const float2*>(qb + 8*D_MODEL + 8);
        hilo2(x0.x, x0.y, Ah[kc][0], Al[kc][0]);
        hilo2(x1.x, x1.y, Ah[kc][1], Al[kc][1]);
        hilo2(x2.x, x2.y, Ah[kc][2], Al[kc][2]);
        hilo2(x3.x, x3.y, Ah[kc][3], Al[kc][3]);
    }

    if (w < 4) {
        // (a) raw band content scores -> Sval (2-term)
        float acc[5][4];
#pragma unroll
        for (int t = 0; t < 5; t++)
#pragma unroll
            for (int e = 0; e < 4; e++) acc[t][e] = 0.f;
#pragma unroll
        for (int tile = 0; tile < 5; tile++) {
            const int jw = rm + tile*8 + g;
#pragma unroll
            for (int kc = 0; kc < 2; kc++) {
                const int c0 = kc*16 + tg*2;
                const uint32_t B0h = hi2(sm->KVw[jw*33 + c0].x,     sm->KVw[jw*33 + c0 + 1].x);
                const uint32_t B1h = hi2(sm->KVw[jw*33 + c0 + 8].x, sm->KVw[jw*33 + c0 + 9].x);
                MMA16816(acc[tile], Ah[kc], B0h, B1h);
                MMA16816(acc[tile], Al[kc], B0h, B1h);
            }
        }
#pragma unroll
        for (int tile = 0; tile < 5; tile++)
#pragma unroll
            for (int e = 0; e < 4; e++) {
                const int r_loc = g + (e >> 1)*8;
                const int jl = tile*8 + tg*2 + (e & 1);
                const int t = jl - r_loc;
                if (t >= 1 && t <= 19)
                    sm->Sval[(rm + r_loc)*22 + t] = acc[tile][e];
            }
        // (b) Osm tiles 0..1 (cols 0..15), 3-term
        float accC[2][4];
#pragma unroll
        for (int t = 0; t < 2; t++)
#pragma unroll
            for (int e = 0; e < 4; e++) accC[t][e] = 0.f;
#pragma unroll
        for (int tile = 0; tile < 2; tile++) {
            const int n = tile*8 + g;
#pragma unroll
            for (int kc = 0; kc < 2; kc++) {
                const int e0 = kc*16 + tg*2;
                const float* cb = &sm->u.Ktv[e0*DH + n];
                uint32_t Bh[2], Bl[2];
                hilo2(cb[0],    cb[DH],   Bh[0], Bl[0]);
                hilo2(cb[8*DH], cb[9*DH], Bh[1], Bl[1]);
                MMA16816(accC[tile], Ah[kc], Bh[0], Bh[1]);
                MMA16816(accC[tile], Al[kc], Bh[0], Bh[1]);
                MMA16816(accC[tile], Ah[kc], Bl[0], Bl[1]);
            }
        }
#pragma unroll
        for (int tile = 0; tile < 2; tile++) {
            const int cc = tile*8 + tg*2;
            const int rr0 = rm + g, rr1 = rr0 + 8;
            sm->Osm[rr0*33 + cc]     = accC[tile][0];
            sm->Osm[rr0*33 + cc + 1] = accC[tile][1];
            sm->Osm[rr1*33 + cc]     = accC[tile][2];
            sm->Osm[rr1*33 + cc + 1] = accC[tile][3];
        }
    } else {
        // (a) Srel = Q.Tk^T (3-term)
        float accR[4][4];
#pragma unroll
        for (int t = 0; t < 4; t++)
#pragma unroll
            for (int e = 0; e < 4; e++) accR[t][e] = 0.f;
#pragma unroll
        for (int tile = 0; tile < 4; tile++) {
            const int n = tile*8 + g;
#pragma unroll
            for (int kc = 0; kc < 2; kc++) {
                const int e0 = kc*16 + tg*2;
                float r0 = 0.f, r1 = 0.f, r2 = 0.f, r3 = 0.f;
                if (n < NT) {
                    const float* tb = &tk[n*32 + e0];
                    r0 = tb[0]; r1 = tb[1]; r2 = tb[8]; r3 = tb[9];
                }
                uint32_t Bh[2], Bl[2];
                hilo2(r0, r1, Bh[0], Bl[0]);
                hilo2(r2, r3, Bh[1], Bl[1]);
                MMA16816(accR[tile], Ah[kc], Bh[0], Bh[1]);
                MMA16816(accR[tile], Al[kc], Bh[0], Bh[1]);
                MMA16816(accR[tile], Ah[kc], Bl[0], Bl[1]);
            }
        }
#pragma unroll
        for (int tile = 0; tile < 4; tile++) {
            const int cc = tile*8 + tg*2;
            const int rr0 = rm + g, rr1 = rr0 + 8;
            if (cc <= 20) {
                sm->Srel[rr0*22 + cc] = accR[tile][0];
                sm->Srel[rr1*22 + cc] = accR[tile][2];
            }
            if (cc + 1 <= 20) {
                sm->Srel[rr0*22 + cc + 1] = accR[tile][1];
                sm->Srel[rr1*22 + cc + 1] = accR[tile][3];
            }
        }
        // (b) Osm tiles 2..3 (cols 16..31), 3-term
        float accC[2][4];
#pragma unroll
        for (int t = 0; t < 2; t++)
#pragma unroll
            for (int e = 0; e < 4; e++) accC[t][e] = 0.f;
#pragma unroll
        for (int tile = 2; tile < 4; tile++) {
            const int n = tile*8 + g;
#pragma unroll
            for (int kc = 0; kc < 2; kc++) {
                const int e0 = kc*16 + tg*2;
                const float* cb = &sm->u.Ktv[e0*DH + n];
                uint32_t Bh[2], Bl[2];
                hilo2(cb[0],    cb[DH],   Bh[0], Bl[0]);
                hilo2(cb[8*DH], cb[9*DH], Bh[1], Bl[1]);
                MMA16816(accC[tile-2], Ah[kc], Bh[0], Bh[1]);
                MMA16816(accC[tile-2], Al[kc], Bh[0], Bh[1]);
                MMA16816(accC[tile-2], Ah[kc], Bl[0], Bl[1]);
            }
        }
#pragma unroll
        for (int tile = 2; tile < 4; tile++) {
            const int cc = tile*8 + tg*2;
            const int rr0 = rm + g, rr1 = rr0 + 8;
            sm->Osm[rr0*33 + cc]     = accC[tile-2][0];
            sm->Osm[rr0*33 + cc + 1] = accC[tile-2][1];
            sm->Osm[rr1*33 + cc]     = accC[tile-2][2];
            sm->Osm[rr1*33 + cc + 1] = accC[tile-2][3];
        }
    }
    __syncthreads();

    // ---------------- phase 2a: band + bucket MMAs -------------------------
    if (w < 4) {
        // Oband[r,d] = sum_t Srel[r,t] * V[r+t, d]   (2-term)
        float acc[4][4];
#pragma unroll
        for (int j = 0; j < 4; j++)
#pragma unroll
            for (int e = 0; e < 4; e++) acc[j][e] = 0.f;
#pragma unroll
        for (int k0 = 0; k0 < 48; k0 += 16) {
            uint32_t A_h[4], A_l[4];
            {
                auto aval = [&](int rl, int kk)->float {
                    const int t = kk - rl;
                    return (t >= 1 && t <= 19) ? sm->Srel[(rm+rl)*22 + t] : 0.f;
                };
                hilo2(aval(g,   k0+tg*2),   aval(g,   k0+tg*2+1), A_h[0], A_l[0]);
                hilo2(aval(g+8, k0+tg*2),   aval(g+8, k0+tg*2+1), A_h[1], A_l[1]);
                hilo2(aval(g,   k0+tg*2+8), aval(g,   k0+tg*2+9), A_h[2], A_l[2]);
                hilo2(aval(g+8, k0+tg*2+8), aval(g+8, k0+tg*2+9), A_h[3], A_l[3]);
            }
#pragma unroll
            for (int j = 0; j < 4; j++) {
                auto vval = [&](int kk)->float {
                    const int row2 = rm + kk;
                    return (row2 < 88) ? sm->KVw[row2*33 + j*8 + g].y : 0.f;
                };
                const uint32_t B0h = hi2(vval(k0+tg*2),   vval(k0+tg*2+1));
                const uint32_t B1h = hi2(vval(k0+tg*2+8), vval(k0+tg*2+9));
                MMA16816(acc[j], A_h, B0h, B1h);
                MMA16816(acc[j], A_l, B0h, B1h);
            }
        }
#pragma unroll
        for (int j = 0; j < 4; j++) {
            const int cc = j*8 + tg*2;
            const int rr0 = rm + g, rr1 = rr0 + 8;
            sm->u.Oband[rr0*33 + cc]     = acc[j][0];
            sm->u.Oband[rr0*33 + cc + 1] = acc[j][1];
            sm->u.Oband[rr1*33 + cc]     = acc[j][2];
            sm->u.Oband[rr1*33 + cc + 1] = acc[j][3];
        }
    } else {
        // Osm[r,d] += sum_t (Sval+Srel masked)[r,t] * Tvs[t,d]   (1-term)
        float acc[4][4];
#pragma unroll
        for (int j = 0; j < 4; j++)
#pragma unroll
            for (int e = 0; e < 4; e++) acc[j][e] = 0.f;
#pragma unroll
        for (int k0 = 0; k0 < 32; k0 += 16) {
            uint32_t A_h[4];
            {
                auto aval = [&](int rl, int t)->float {
                    if (t < 1 || t > 19) return 0.f;
                    const int rr = rm + rl;
                    const int kidx = q0 + rr + t - MAXREL;
                    return (kidx >= 0 && kidx < SEQ)
                        ? (sm->Sval[rr*22 + t] + sm->Srel[rr*22 + t]) : 0.f;
                };
                A_h[0] = hi2(aval(g,   k0+tg*2),   aval(g,   k0+tg*2+1));
                A_h[1] = hi2(aval(g+8, k0+tg*2),   aval(g+8, k0+tg*2+1));
                A_h[2] = hi2(aval(g,   k0+tg*2+8), aval(g,   k0+tg*2+9));
                A_h[3] = hi2(aval(g+8, k0+tg*2+8), aval(g+8, k0+tg*2+9));
            }
#pragma unroll
            for (int j = 0; j < 4; j++) {
                auto tvv = [&](int t)->float {
                    return (t < NT) ? sm->Tvs[t*33 + j*8 + g] : 0.f;
                };
                const uint32_t B0h = hi2(tvv(k0+tg*2),   tvv(k0+tg*2+1));
                const uint32_t B1h = hi2(tvv(k0+tg*2+8), tvv(k0+tg*2+9));
                MMA16816(acc[j], A_h, B0h, B1h);
            }
        }
#pragma unroll
        for (int j = 0; j < 4; j++) {
            const int cc = j*8 + tg*2;
            const int rr0 = rm + g, rr1 = rr0 + 8;
            sm->Osm[rr0*33 + cc]     += acc[j][0];
            sm->Osm[rr0*33 + cc + 1] += acc[j][1];
            sm->Osm[rr1*33 + cc]     += acc[j][2];
            sm->Osm[rr1*33 + cc + 1] += acc[j][3];
        }
    }

    // ---------------- scan A: local 11-row sums (raw KVw reads) ------------
    {
        const int j0 = w * 11;
        const int jend = (j0 + 11 < 84) ? j0 + 11 : 84;
        float sk = 0.f, sv = 0.f;
        for (int j = j0; j < jend; j++) {
            const float2 p = sm->KVw[j*33 + lane];
            sk += p.x; sv += p.y;
        }
        sm->scanTmp[w*32 + lane] = make_float2(sk, sv);
    }
    __syncthreads();

    // ---------------- scan B: in-place inclusive prefix over rows 0..83 ----
    {
        float rk = 0.f, rv = 0.f;
        for (int w2 = 0; w2 < w; w2++) {
            const float2 p = sm->scanTmp[w2*32 + lane];
            rk += p.x; rv += p.y;
        }
        const int j0 = w * 11;
        const int jend = (j0 + 11 < 84) ? j0 + 11 : 84;
        for (int j = j0; j < jend; j++) {
            const float2 p = sm->KVw[j*33 + lane];
            rk += p.x; rv += p.y;
            sm->KVw[j*33 + lane] = make_float2(rk, rv);
        }
    }
    __syncthreads();

    // ---------------- phase 2b: thin scalar tail ---------------------------
    const float ktot = sm->ktotS[lane];
    const float vtot = sm->vtotS[lane];
    const float2 p9 = sm->KVw[9*33 + lane];
    const float baseK = sm->offK[lane] - p9.x, baseV = sm->offV[lane] - p9.y;

    for (int iq = 0; iq < 8; iq++) {
        const int r = iq*8 + w, q = q0 + r;
        const float2 Pr   = sm->KVw[r*33 + lane];
        const float2 Pr19 = sm->KVw[(r+19)*33 + lane];
        const float k1 = baseK + Pr.x,   v1 = baseV + Pr.y;
        const float k2 = baseK + Pr19.x, v2 = baseV + Pr19.y;

        const float qreg = g_Qp[((size_t)(b*SEQ + q))*D_MODEL + h*DH + lane];

        float pp = qreg * k1;
        float ss = qreg * (ktot - k2);
#pragma unroll
        for (int off = 16; off > 0; off >>= 1) {
            pp += __shfl_xor_sync(0xffffffffu, pp, off);
            ss += __shfl_xor_sync(0xffffffffu, ss, off);
        }

        const float s0  = sm->Srel[r*22 + 0];
        const float s20 = sm->Srel[r*22 + 20];
        float wv = sm->Osm[r*33 + lane] + sm->u.Oband[r*33 + lane]
                 + s0*v1 + s20*(vtot - v2);
        const float Sv0  = (q - MAXREL >= 0) ? (pp + (float)(q - MAXREL + 1)*s0) : 0.f;
        const float Sv20 = (q + MAXREL <= SEQ-1) ? (ss + (float)(SEQ - q - MAXREL)*s20) : 0.f;
        wv += Sv0 * sm->Tvs[lane] + Sv20 * sm->Tvs[20*33 + lane];

        const float o = wv * INV_SCALE;
        const __nv_bfloat16 hi = __float2bfloat16(o);
        const __nv_bfloat16 lo = __float2bfloat16(o - __bfloat162float(hi));
        const size_t rb = ((size_t)(b*SEQ + q))*X2W + h*DH + lane;
        g_X2[rb]       = hi;
        g_X2[rb + 256] = lo;
    }
}

// ============================================================================
// launch
// ============================================================================
extern "C" void kernel_launch(void* const* d_in, const int* in_sizes, int n_in,
                              void* d_out, int out_size)
{
    const float* q   = (const float*)d_in[0];
    const float* k   = (const float*)d_in[1];
    const float* v   = (const float*)d_in[2];
    const float* Wq  = (const float*)d_in[4];
    const float* bq  = (const float*)d_in[5];
    const float* Wk  = (const float*)d_in[6];
    const float* bk  = (const float*)d_in[7];
    const float* Wv  = (const float*)d_in[8];
    const float* bv  = (const float*)d_in[9];
    const float* W0  = (const float*)d_in[10];
    const float* b0  = (const float*)d_in[11];
    const float* tk  = (const float*)d_in[12];
    const float* tv  = (const float*)d_in[13];
    float* out = (float*)d_out;

    static int attr_done = 0;
    if (!attr_done) {
        cudaFuncSetAttribute(proj_kv_mma, cudaFuncAttributeMaxDynamicSharedMemorySize,
                             (int)sizeof(GemmSmem));
        cudaFuncSetAttribute(mid_kernel, cudaFuncAttributeMaxDynamicSharedMemorySize,
                             (int)sizeof(GemmSmem));
        cudaFuncSetAttribute(final_mma, cudaFuncAttributeMaxDynamicSharedMemorySize,
                             (int)sizeof(Gemm64Smem));
        cudaFuncSetAttribute(stage3, cudaFuncAttributeMaxDynamicSharedMemorySize,
                             (int)sizeof(S3Smem));
        attr_done = 1;
    }

    proj_kv_mma<<<dim3(MROWS/128, D_MODEL/64, 2), 256, sizeof(GemmSmem)>>>(
                   k, v, Wk, bk, Wv, bv);
    mid_kernel <<<386, 256, sizeof(GemmSmem)>>>(q, Wq, bq, W0);
    stage3     <<<dim3(SEQ/QT, BHN), 256, sizeof(S3Smem)>>>(tk, tv);
    final_mma  <<<dim3(MROWS/64, D_MODEL/64), 256, sizeof(Gemm64Smem)>>>(b0, out);
}